// round 1
// baseline (speedup 1.0000x reference)
#include <cuda_runtime.h>
#include <cuda_fp8.h>
#include <math.h>
#include <float.h>

// Problem dims (fixed)
#define BB 4
#define TT 2048
#define CC 1280
#define HH 10
#define DD 128
#define FF 5120
#define NROWS (BB*TT)        // 8192
#define EPSV 1e-5f

// ---------------- scratch (static device allocations; no cudaMalloc) ----------------
__device__ float g_xn  [NROWS*CC];       // rmsnorm output (reused for ln2)
__device__ float g_qkv [NROWS*3*CC];     // qkv projection
__device__ float g_q   [BB*HH*TT*DD];    // processed q (b,h,t,d)
__device__ float g_k   [BB*HH*TT*DD];
__device__ float g_v   [BB*HH*TT*DD];
__device__ float g_attn[NROWS*CC];       // attention out (b,t,h*d)
__device__ float g_x1  [NROWS*CC];       // after first residual
__device__ float g_h   [NROWS*FF];       // MLP hidden

// ---------------- RMSNorm over C=1280 ----------------
__global__ __launch_bounds__(256) void rmsnorm_k(const float* __restrict__ x,
                                                 const float* __restrict__ w,
                                                 float* __restrict__ y) {
    int row = blockIdx.x;
    const float* xr = x + (size_t)row * CC;
    float v[5];
    float ss = 0.f;
#pragma unroll
    for (int i = 0; i < 5; i++) {
        v[i] = xr[threadIdx.x + i * 256];
        ss += v[i] * v[i];
    }
#pragma unroll
    for (int o = 16; o > 0; o >>= 1) ss += __shfl_xor_sync(0xffffffffu, ss, o);
    __shared__ float sh[8];
    if ((threadIdx.x & 31) == 0) sh[threadIdx.x >> 5] = ss;
    __syncthreads();
    float tot = 0.f;
#pragma unroll
    for (int i = 0; i < 8; i++) tot += sh[i];
    float inv = rsqrtf(tot / (float)CC + EPSV);
    float* yr = y + (size_t)row * CC;
#pragma unroll
    for (int i = 0; i < 5; i++)
        yr[threadIdx.x + i * 256] = v[i] * inv * w[threadIdx.x + i * 256];
}

// ---------------- tiled fp32 GEMM 128x128x8, 256 threads, 8x8/thread ----------------
// EPI: 0 = store, 1 = store residual+acc, 2 = store relu(acc)^2
template <int EPI>
__global__ __launch_bounds__(256) void sgemm_k(const float* __restrict__ A,
                                               const float* __restrict__ B,
                                               float* __restrict__ C,
                                               const float* __restrict__ R,
                                               int M, int N, int K) {
    __shared__ float As[8][128];   // transposed A tile: As[k][m]
    __shared__ float Bs[8][128];   // Bs[k][n]
    int tid = threadIdx.x;
    int ty = tid >> 4, tx = tid & 15;
    int by = blockIdx.y, bx = blockIdx.x;

    int aRow = tid >> 1;
    int aCol = (tid & 1) * 4;
    const float* Ag = A + (size_t)(by * 128 + aRow) * K + aCol;
    int bRow = tid >> 5;
    int bCol = (tid & 31) * 4;
    const float* Bg = B + (size_t)bRow * N + bx * 128 + bCol;

    float acc[8][8];
#pragma unroll
    for (int i = 0; i < 8; i++)
#pragma unroll
        for (int j = 0; j < 8; j++) acc[i][j] = 0.f;

    for (int k0 = 0; k0 < K; k0 += 8) {
        float4 av = *(const float4*)(Ag + k0);
        float4 bv = *(const float4*)(Bg + (size_t)k0 * N);
        As[aCol + 0][aRow] = av.x;
        As[aCol + 1][aRow] = av.y;
        As[aCol + 2][aRow] = av.z;
        As[aCol + 3][aRow] = av.w;
        *(float4*)&Bs[bRow][bCol] = bv;
        __syncthreads();
#pragma unroll
        for (int kk = 0; kk < 8; kk++) {
            float4 a0 = *(const float4*)&As[kk][ty * 4];
            float4 a1 = *(const float4*)&As[kk][64 + ty * 4];
            float4 b0 = *(const float4*)&Bs[kk][tx * 4];
            float4 b1 = *(const float4*)&Bs[kk][64 + tx * 4];
            float a[8] = {a0.x, a0.y, a0.z, a0.w, a1.x, a1.y, a1.z, a1.w};
            float b[8] = {b0.x, b0.y, b0.z, b0.w, b1.x, b1.y, b1.z, b1.w};
#pragma unroll
            for (int i = 0; i < 8; i++)
#pragma unroll
                for (int j = 0; j < 8; j++) acc[i][j] += a[i] * b[j];
        }
        __syncthreads();
    }

#pragma unroll
    for (int i = 0; i < 8; i++) {
        int row = by * 128 + ((i < 4) ? (ty * 4 + i) : (64 + ty * 4 + (i - 4)));
#pragma unroll
        for (int jh = 0; jh < 2; jh++) {
            size_t idx = (size_t)row * N + bx * 128 + jh * 64 + tx * 4;
            float4 r;
            r.x = acc[i][jh * 4 + 0];
            r.y = acc[i][jh * 4 + 1];
            r.z = acc[i][jh * 4 + 2];
            r.w = acc[i][jh * 4 + 3];
            if (EPI == 1) {
                float4 rv = *(const float4*)(R + idx);
                r.x += rv.x; r.y += rv.y; r.z += rv.z; r.w += rv.w;
            }
            if (EPI == 2) {
                r.x = fmaxf(r.x, 0.f); r.x *= r.x;
                r.y = fmaxf(r.y, 0.f); r.y *= r.y;
                r.z = fmaxf(r.z, 0.f); r.z *= r.z;
                r.w = fmaxf(r.w, 0.f); r.w *= r.w;
            }
            *(float4*)(C + idx) = r;
        }
    }
}

// ---------------- RoPE + per-head RMSNorm + MXFP8 quant-dequant ----------------
// grid: (3*H, T, B); block 128 threads (one per d). which = q/k/v.
__global__ __launch_bounds__(128) void qkvpost_k(const float* __restrict__ qkv,
                                                 const float* __restrict__ rope,
                                                 const float* __restrict__ qn_w,
                                                 const float* __restrict__ kn_w,
                                                 float* __restrict__ Q,
                                                 float* __restrict__ K,
                                                 float* __restrict__ V) {
    int which = blockIdx.x / HH;   // 0=q 1=k 2=v
    int h = blockIdx.x % HH;
    int t = blockIdx.y;
    int b = blockIdx.z;
    int d = threadIdx.x;
    size_t row = (size_t)b * TT + t;
    float v = qkv[row * (3 * CC) + which * CC + h * DD + d];

    __shared__ float sh[DD];
    __shared__ float red[4];

    if (which < 2) {
        // rotate-half RoPE
        sh[d] = v;
        __syncthreads();
        float fr = rope[(size_t)t * DD + d];
        float partner = (d < 64) ? -sh[d + 64] : sh[d - 64];
        v = v * cosf(fr) + partner * sinf(fr);
        // per-head rmsnorm over D=128
        float ss = v * v;
#pragma unroll
        for (int o = 16; o > 0; o >>= 1) ss += __shfl_xor_sync(0xffffffffu, ss, o);
        if ((d & 31) == 0) red[d >> 5] = ss;
        __syncthreads();
        float tot = red[0] + red[1] + red[2] + red[3];
        v *= rsqrtf(tot / 128.f + EPSV) * ((which == 0) ? qn_w[d] : kn_w[d]);
    }

    // MXFP8 quant-dequant: one 32-element block == one warp
    float a = fabsf(v);
#pragma unroll
    for (int o = 16; o > 0; o >>= 1) a = fmaxf(a, __shfl_xor_sync(0xffffffffu, a, o));
    a = fmaxf(a, 1e-12f);
    int se = (int)floorf(log2f(a)) + 119;   // +127-8
    se = min(max(se, 0), 255);
    float scale = exp2f((float)(127 - se));
    float qv = fminf(fmaxf(v * scale, -448.f), 448.f);
    float dq = (float)__nv_fp8_e4m3(qv) * exp2f((float)(se - 127));

    size_t oidx = (((size_t)b * HH + h) * TT + t) * DD + d;
    if (which == 0)      Q[oidx] = dq;
    else if (which == 1) K[oidx] = dq;
    else                 V[oidx] = dq;
}

// ---------------- causal flash attention, fp32, 64x64 tiles ----------------
// smem: Qt[128][68] + Kt[128][68] + Vs[64][132] + Pt[64][68]  = 120832 B
#define FLASH_SMEM 120832
__global__ __launch_bounds__(256) void flash_k(const float* __restrict__ Qg,
                                               const float* __restrict__ Kg,
                                               const float* __restrict__ Vg,
                                               float* __restrict__ O) {
    int qt = blockIdx.x, h = blockIdx.y, b = blockIdx.z;
    extern __shared__ float sm[];
    float* Qt = sm;                 // [128][68] transposed
    float* Kt = Qt + 128 * 68;      // [128][68] transposed
    float* Vs = Kt + 128 * 68;      // [64][132]
    float* Pt = Vs + 64 * 132;      // [64][68] transposed P

    int tid = threadIdx.x, ty = tid >> 4, tx = tid & 15;
    const float* Qb = Qg + (((size_t)b * HH + h) * TT + qt * 64) * DD;
    const float* Kb = Kg + ((size_t)b * HH + h) * TT * DD;
    const float* Vb = Vg + ((size_t)b * HH + h) * TT * DD;

#pragma unroll
    for (int i = 0; i < 32; i++) {
        int lin = tid + i * 256;
        int r = lin >> 7, k = lin & 127;
        Qt[k * 68 + r] = Qb[(size_t)r * DD + k];
    }

    float o[4][8];
    float m_[4], l_[4];
#pragma unroll
    for (int i = 0; i < 4; i++) {
        m_[i] = -FLT_MAX; l_[i] = 0.f;
#pragma unroll
        for (int j = 0; j < 8; j++) o[i][j] = 0.f;
    }
    const float smscale = 0.08838834764831845f;  // 1/sqrt(128)

    for (int kv = 0; kv <= qt; kv++) {
        __syncthreads();  // also protects Vs/Pt from previous iteration
        const float* Kp = Kb + (size_t)kv * 64 * DD;
        const float* Vp = Vb + (size_t)kv * 64 * DD;
#pragma unroll
        for (int i = 0; i < 32; i++) {
            int lin = tid + i * 256;
            int r = lin >> 7, k = lin & 127;
            Kt[k * 68 + r] = Kp[(size_t)r * DD + k];
            Vs[r * 132 + k] = Vp[(size_t)r * DD + k];
        }
        __syncthreads();

        float s[4][4];
#pragma unroll
        for (int i = 0; i < 4; i++)
#pragma unroll
            for (int j = 0; j < 4; j++) s[i][j] = 0.f;

#pragma unroll 8
        for (int k = 0; k < 128; k++) {
            float4 aq = *(const float4*)&Qt[k * 68 + ty * 4];
            float4 bk = *(const float4*)&Kt[k * 68 + tx * 4];
            float av[4] = {aq.x, aq.y, aq.z, aq.w};
            float bv[4] = {bk.x, bk.y, bk.z, bk.w};
#pragma unroll
            for (int i = 0; i < 4; i++)
#pragma unroll
                for (int j = 0; j < 4; j++) s[i][j] += av[i] * bv[j];
        }

#pragma unroll
        for (int i = 0; i < 4; i++)
#pragma unroll
            for (int j = 0; j < 4; j++) {
                s[i][j] *= smscale;
                if (kv == qt && (tx * 4 + j) > (ty * 4 + i)) s[i][j] = -FLT_MAX;
            }

        // online softmax (row stats shared among 16 lanes w/ same ty)
        float p[4][4];
#pragma unroll
        for (int i = 0; i < 4; i++) {
            float mt = fmaxf(fmaxf(s[i][0], s[i][1]), fmaxf(s[i][2], s[i][3]));
#pragma unroll
            for (int o2 = 8; o2 > 0; o2 >>= 1) mt = fmaxf(mt, __shfl_xor_sync(0xffffffffu, mt, o2));
            float mnew = fmaxf(m_[i], mt);
            float alpha = expf(m_[i] - mnew);
            float rs = 0.f;
#pragma unroll
            for (int j = 0; j < 4; j++) {
                p[i][j] = expf(s[i][j] - mnew);
                rs += p[i][j];
            }
#pragma unroll
            for (int o2 = 8; o2 > 0; o2 >>= 1) rs += __shfl_xor_sync(0xffffffffu, rs, o2);
            l_[i] = l_[i] * alpha + rs;
            m_[i] = mnew;
#pragma unroll
            for (int jj = 0; jj < 8; jj++) o[i][jj] *= alpha;
        }

        // publish P (transposed)
#pragma unroll
        for (int i = 0; i < 4; i++)
#pragma unroll
            for (int j = 0; j < 4; j++)
                Pt[(tx * 4 + j) * 68 + ty * 4 + i] = p[i][j];
        __syncthreads();

        // O += P @ V  (thread cols: tx + 16*jj)
#pragma unroll 4
        for (int j = 0; j < 64; j++) {
            float4 pv = *(const float4*)&Pt[j * 68 + ty * 4];
#pragma unroll
            for (int jj = 0; jj < 8; jj++) {
                float vv = Vs[j * 132 + tx + 16 * jj];
                o[0][jj] += pv.x * vv;
                o[1][jj] += pv.y * vv;
                o[2][jj] += pv.z * vv;
                o[3][jj] += pv.w * vv;
            }
        }
    }

#pragma unroll
    for (int i = 0; i < 4; i++) {
        int trow = qt * 64 + ty * 4 + i;
        float invl = 1.f / l_[i];
        size_t base = ((size_t)b * TT + trow) * CC + h * DD;
#pragma unroll
        for (int jj = 0; jj < 8; jj++)
            O[base + tx + 16 * jj] = o[i][jj] * invl;
    }
}

// ---------------- launcher ----------------
extern "C" void kernel_launch(void* const* d_in, const int* in_sizes, int n_in,
                              void* d_out, int out_size) {
    const float* x    = (const float*)d_in[0];
    const float* rope = (const float*)d_in[1];
    const float* ln1  = (const float*)d_in[2];
    const float* wqkv = (const float*)d_in[3];
    const float* qnw  = (const float*)d_in[4];
    const float* knw  = (const float*)d_in[5];
    const float* wout = (const float*)d_in[6];
    const float* ln2  = (const float*)d_in[7];
    const float* wfc1 = (const float*)d_in[8];
    const float* wfc2 = (const float*)d_in[9];
    float* out = (float*)d_out;

    float *xn, *qkv, *q, *k, *v, *attn, *x1, *hb;
    cudaGetSymbolAddress((void**)&xn,   g_xn);
    cudaGetSymbolAddress((void**)&qkv,  g_qkv);
    cudaGetSymbolAddress((void**)&q,    g_q);
    cudaGetSymbolAddress((void**)&k,    g_k);
    cudaGetSymbolAddress((void**)&v,    g_v);
    cudaGetSymbolAddress((void**)&attn, g_attn);
    cudaGetSymbolAddress((void**)&x1,   g_x1);
    cudaGetSymbolAddress((void**)&hb,   g_h);

    cudaFuncSetAttribute(flash_k, cudaFuncAttributeMaxDynamicSharedMemorySize, FLASH_SMEM);

    // 1. ln1
    rmsnorm_k<<<NROWS, 256>>>(x, ln1, xn);
    // 2. qkv = xn @ w_qkv
    {
        dim3 g(3 * CC / 128, NROWS / 128);
        sgemm_k<0><<<g, 256>>>(xn, wqkv, qkv, nullptr, NROWS, 3 * CC, CC);
    }
    // 3. rope + head-norm + mxfp8 qdq
    {
        dim3 g(3 * HH, TT, BB);
        qkvpost_k<<<g, 128>>>(qkv, rope, qnw, knw, q, k, v);
    }
    // 4. causal flash attention
    {
        dim3 g(TT / 64, HH, BB);
        flash_k<<<g, 256, FLASH_SMEM>>>(q, k, v, attn);
    }
    // 5. x1 = x + attn @ w_out
    {
        dim3 g(CC / 128, NROWS / 128);
        sgemm_k<1><<<g, 256>>>(attn, wout, x1, x, NROWS, CC, CC);
    }
    // 6. ln2
    rmsnorm_k<<<NROWS, 256>>>(x1, ln2, xn);
    // 7. h = srelu(xn @ w_fc1)
    {
        dim3 g(FF / 128, NROWS / 128);
        sgemm_k<2><<<g, 256>>>(xn, wfc1, hb, nullptr, NROWS, FF, CC);
    }
    // 8. out = x1 + h @ w_fc2
    {
        dim3 g(CC / 128, NROWS / 128);
        sgemm_k<1><<<g, 256>>>(hb, wfc2, out, x1, NROWS, CC, FF);
    }
}

// round 4
// speedup vs baseline: 2.1586x; 2.1586x over previous
#include <cuda_runtime.h>
#include <cuda_bf16.h>
#include <cuda_fp8.h>
#include <math.h>
#include <float.h>
#include <stdint.h>

// Problem dims (fixed)
#define BB 4
#define TT 2048
#define CC 1280
#define HH 10
#define DD 128
#define FF 5120
#define NROWS (BB*TT)        // 8192
#define EPSV 1e-5f

// ================= PTX helpers =================
__device__ __forceinline__ uint32_t s2u(const void* p) {
    uint32_t a;
    asm("{ .reg .u64 t; cvta.to.shared.u64 t, %1; cvt.u32.u64 %0, t; }" : "=r"(a) : "l"(p));
    return a;
}
#define CP16(dst, src) \
    asm volatile("cp.async.cg.shared.global [%0], [%1], 16;" :: "r"(dst), "l"(src))
#define CPCOMMIT() asm volatile("cp.async.commit_group;")

#define LDSM4(r0, r1, r2, r3, addr) \
    asm volatile("ldmatrix.sync.aligned.m8n8.x4.shared.b16 {%0,%1,%2,%3}, [%4];" \
        : "=r"(r0), "=r"(r1), "=r"(r2), "=r"(r3) : "r"(addr))

#define MMA16816(d, a, b) \
    asm volatile("mma.sync.aligned.m16n8k16.row.col.f32.bf16.bf16.f32 " \
        "{%0,%1,%2,%3}, {%4,%5,%6,%7}, {%8,%9}, {%0,%1,%2,%3};" \
        : "+f"((d)[0]), "+f"((d)[1]), "+f"((d)[2]), "+f"((d)[3]) \
        : "r"((a)[0]), "r"((a)[1]), "r"((a)[2]), "r"((a)[3]), "r"((b)[0]), "r"((b)[1]))

__device__ __forceinline__ uint32_t swz(uint32_t off) {  // SW128 within 128B rows
    return off ^ ((off >> 3) & 0x70);
}

// ================= scratch =================
__device__ float g_qkv [NROWS * 3 * CC];
__device__ float g_q   [BB * HH * TT * DD];
__device__ float g_k   [BB * HH * TT * DD];
__device__ float g_v   [BB * HH * TT * DD];
__device__ float g_attn[NROWS * CC];
__device__ float g_x1  [NROWS * CC];

__device__ __nv_bfloat16 g_xn_hi[NROWS * CC],   g_xn_lo[NROWS * CC];
__device__ __nv_bfloat16 g_at_hi[NROWS * CC],   g_at_lo[NROWS * CC];
__device__ __nv_bfloat16 g_h_hi [NROWS * FF],   g_h_lo [NROWS * FF];
__device__ __nv_bfloat16 g_wq_hi[3 * CC * CC],  g_wq_lo[3 * CC * CC];
__device__ __nv_bfloat16 g_wo_hi[CC * CC],      g_wo_lo[CC * CC];
__device__ __nv_bfloat16 g_w1_hi[FF * CC],      g_w1_lo[FF * CC];
__device__ __nv_bfloat16 g_w2_hi[CC * FF],      g_w2_lo[CC * FF];

// ================= weight prep: W[K,N] fp32 -> Whi/Wlo [N,K] bf16 =================
__global__ __launch_bounds__(256) void wprep_k(const float* __restrict__ W,
                                               __nv_bfloat16* __restrict__ Whi,
                                               __nv_bfloat16* __restrict__ Wlo,
                                               int K, int N) {
    __shared__ float t[32][33];
    int n0 = blockIdx.x * 32, k0 = blockIdx.y * 32;
    int tx = threadIdx.x & 31, ty = threadIdx.x >> 5;
#pragma unroll
    for (int i = ty; i < 32; i += 8)
        t[i][tx] = W[(size_t)(k0 + i) * N + n0 + tx];
    __syncthreads();
#pragma unroll
    for (int i = ty; i < 32; i += 8) {
        float v = t[tx][i];
        __nv_bfloat16 h = __float2bfloat16(v);
        __nv_bfloat16 l = __float2bfloat16(v - __bfloat162float(h));
        size_t o = (size_t)(n0 + i) * K + k0 + tx;
        Whi[o] = h; Wlo[o] = l;
    }
}

// ================= fp32 -> hi/lo bf16 elementwise =================
__global__ __launch_bounds__(256) void cvt_hilo_k(const float* __restrict__ x,
                                                  __nv_bfloat16* __restrict__ hi,
                                                  __nv_bfloat16* __restrict__ lo,
                                                  int n) {
    for (int i = blockIdx.x * 256 + threadIdx.x; i < n; i += gridDim.x * 256) {
        float v = x[i];
        __nv_bfloat16 h = __float2bfloat16(v);
        hi[i] = h;
        lo[i] = __float2bfloat16(v - __bfloat162float(h));
    }
}

// ================= RMSNorm over C=1280, emits hi/lo bf16 =================
__global__ __launch_bounds__(256) void rmsnorm_k(const float* __restrict__ x,
                                                 const float* __restrict__ w,
                                                 __nv_bfloat16* __restrict__ yhi,
                                                 __nv_bfloat16* __restrict__ ylo) {
    int row = blockIdx.x;
    const float* xr = x + (size_t)row * CC;
    float v[5];
    float ss = 0.f;
#pragma unroll
    for (int i = 0; i < 5; i++) {
        v[i] = xr[threadIdx.x + i * 256];
        ss += v[i] * v[i];
    }
#pragma unroll
    for (int o = 16; o > 0; o >>= 1) ss += __shfl_xor_sync(0xffffffffu, ss, o);
    __shared__ float sh[8];
    if ((threadIdx.x & 31) == 0) sh[threadIdx.x >> 5] = ss;
    __syncthreads();
    float tot = 0.f;
#pragma unroll
    for (int i = 0; i < 8; i++) tot += sh[i];
    float inv = rsqrtf(tot / (float)CC + EPSV);
#pragma unroll
    for (int i = 0; i < 5; i++) {
        int c = threadIdx.x + i * 256;
        float y = v[i] * inv * w[c];
        __nv_bfloat16 h = __float2bfloat16(y);
        size_t o = (size_t)row * CC + c;
        yhi[o] = h;
        ylo[o] = __float2bfloat16(y - __bfloat162float(h));
    }
}

// ================= HMMA split-bf16 GEMM =================
// D[M,N] = A[M,K] @ W[K,N]; A as Ahi/Alo [M,K] bf16, W as Bhi/Blo [N,K] bf16.
// 3-term: AhBh + AhBl + AlBh.  Tile 128x128x64, 2-stage cp.async, 8 warps
// (2M x 4N), warp tile 64x32 = 4x4 m16n8k16.
// EPI: 0 = fp32 store; 1 = fp32 acc+R; 2 = srelu -> hi/lo bf16.
#define GT 256
#define STG_SZ 65536u
#define GEMM_SMEM (2 * 65536)

template <int EPI>
__global__ __launch_bounds__(GT) void gemm_k(const __nv_bfloat16* __restrict__ Ahi,
                                             const __nv_bfloat16* __restrict__ Alo,
                                             const __nv_bfloat16* __restrict__ Bhi,
                                             const __nv_bfloat16* __restrict__ Blo,
                                             float* __restrict__ Cf,
                                             const float* __restrict__ R,
                                             __nv_bfloat16* __restrict__ Chi,
                                             __nv_bfloat16* __restrict__ Clo,
                                             int M, int N, int K) {
    extern __shared__ __align__(128) char sm_raw[];
    uint32_t smb = s2u(sm_raw);
    const uint32_t oAhi = 0, oAlo = 16384, oBhi = 32768, oBlo = 49152;
    int tid = threadIdx.x;
    int lane = tid & 31, wid = tid >> 5;
    int wm = wid >> 2, wn = wid & 3;         // warp grid 2(M) x 4(N)
    int m0 = blockIdx.y * 128, n0 = blockIdx.x * 128;
    int m0w = wm * 64, n0w = wn * 32;
    int KB = K >> 6;

    int lrow = tid >> 3;
    int lch = tid & 7;

    auto load_stage = [&](int z, int kb) {
        uint32_t base = smb + (uint32_t)z * STG_SZ;
        size_t kof = (size_t)kb * 64;
#pragma unroll
        for (int i = 0; i < 4; i++) {
            int row = lrow + i * 32;
            uint32_t so = swz((uint32_t)(row * 128 + lch * 16));
            size_t goA = (size_t)(m0 + row) * K + kof + lch * 8;
            size_t goB = (size_t)(n0 + row) * K + kof + lch * 8;
            CP16(base + oAhi + so, Ahi + goA);
            CP16(base + oAlo + so, Alo + goA);
            CP16(base + oBhi + so, Bhi + goB);
            CP16(base + oBlo + so, Blo + goB);
        }
        CPCOMMIT();
    };

    float acc[4][4][4];
#pragma unroll
    for (int i = 0; i < 4; i++)
#pragma unroll
        for (int j = 0; j < 4; j++)
#pragma unroll
            for (int r = 0; r < 4; r++) acc[i][j][r] = 0.f;

    uint32_t aoff = swz((uint32_t)((m0w + (lane & 15)) * 128 + (lane >> 4) * 16));
    uint32_t boff = swz((uint32_t)((n0w + ((lane >> 3) >> 1) * 8 + (lane & 7)) * 128 +
                                   ((lane >> 3) & 1) * 16));

    load_stage(0, 0);

    for (int kb = 0; kb < KB; kb++) {
        int s = kb & 1;
        if (kb + 1 < KB) {
            load_stage(s ^ 1, kb + 1);
            asm volatile("cp.async.wait_group 1;");
        } else {
            asm volatile("cp.async.wait_group 0;");
        }
        __syncthreads();

        uint32_t base = smb + (uint32_t)s * STG_SZ;
#pragma unroll
        for (int ks = 0; ks < 4; ks++) {
            uint32_t kbyte = (uint32_t)ks * 32;   // 16 elems * 2B
            uint32_t ah[4][4], al[4][4], bh[4][2], bl[4][2];
#pragma unroll
            for (int mt = 0; mt < 4; mt++) {
                uint32_t ad = base + ((aoff + mt * 16 * 128) ^ kbyte);
                LDSM4(ah[mt][0], ah[mt][1], ah[mt][2], ah[mt][3], ad + oAhi);
                LDSM4(al[mt][0], al[mt][1], al[mt][2], al[mt][3], ad + oAlo);
            }
#pragma unroll
            for (int bt = 0; bt < 2; bt++) {
                uint32_t bd = base + ((boff + bt * 16 * 128) ^ kbyte);
                LDSM4(bh[bt * 2][0], bh[bt * 2][1], bh[bt * 2 + 1][0], bh[bt * 2 + 1][1], bd + oBhi);
                LDSM4(bl[bt * 2][0], bl[bt * 2][1], bl[bt * 2 + 1][0], bl[bt * 2 + 1][1], bd + oBlo);
            }
#pragma unroll
            for (int mt = 0; mt < 4; mt++)
#pragma unroll
                for (int nt = 0; nt < 4; nt++) {
                    MMA16816(acc[mt][nt], ah[mt], bh[nt]);
                    MMA16816(acc[mt][nt], ah[mt], bl[nt]);
                    MMA16816(acc[mt][nt], al[mt], bh[nt]);
                }
        }
        __syncthreads();
    }

    int r4 = lane >> 2, c2 = (lane & 3) * 2;
#pragma unroll
    for (int mt = 0; mt < 4; mt++) {
#pragma unroll
        for (int half = 0; half < 2; half++) {
            int row = m0 + m0w + mt * 16 + r4 + half * 8;
#pragma unroll
            for (int nt = 0; nt < 4; nt++) {
                int col = n0 + n0w + nt * 8 + c2;
                size_t idx = (size_t)row * N + col;
                float v0 = acc[mt][nt][half * 2 + 0];
                float v1 = acc[mt][nt][half * 2 + 1];
                if (EPI == 0 || EPI == 1) {
                    if (EPI == 1) {
                        float2 rv = *(const float2*)(R + idx);
                        v0 += rv.x; v1 += rv.y;
                    }
                    float2 o; o.x = v0; o.y = v1;
                    *(float2*)(Cf + idx) = o;
                } else {
                    v0 = fmaxf(v0, 0.f); v0 *= v0;
                    v1 = fmaxf(v1, 0.f); v1 *= v1;
                    __nv_bfloat16 h0 = __float2bfloat16(v0);
                    __nv_bfloat16 h1 = __float2bfloat16(v1);
                    __nv_bfloat162 hp; hp.x = h0; hp.y = h1;
                    __nv_bfloat162 lp;
                    lp.x = __float2bfloat16(v0 - __bfloat162float(h0));
                    lp.y = __float2bfloat16(v1 - __bfloat162float(h1));
                    *(__nv_bfloat162*)(Chi + idx) = hp;
                    *(__nv_bfloat162*)(Clo + idx) = lp;
                }
            }
        }
    }
}

// ================= RoPE + per-head RMSNorm + MXFP8 quant-dequant =================
__global__ __launch_bounds__(128) void qkvpost_k(const float* __restrict__ qkv,
                                                 const float* __restrict__ rope,
                                                 const float* __restrict__ qn_w,
                                                 const float* __restrict__ kn_w,
                                                 float* __restrict__ Q,
                                                 float* __restrict__ K,
                                                 float* __restrict__ V) {
    int which = blockIdx.x / HH;
    int h = blockIdx.x % HH;
    int t = blockIdx.y;
    int b = blockIdx.z;
    int d = threadIdx.x;
    size_t row = (size_t)b * TT + t;
    float v = qkv[row * (3 * CC) + which * CC + h * DD + d];

    __shared__ float sh[DD];
    __shared__ float red[4];

    if (which < 2) {
        sh[d] = v;
        __syncthreads();
        float fr = rope[(size_t)t * DD + d];
        float partner = (d < 64) ? -sh[d + 64] : sh[d - 64];
        v = v * cosf(fr) + partner * sinf(fr);
        float ss = v * v;
#pragma unroll
        for (int o = 16; o > 0; o >>= 1) ss += __shfl_xor_sync(0xffffffffu, ss, o);
        if ((d & 31) == 0) red[d >> 5] = ss;
        __syncthreads();
        float tot = red[0] + red[1] + red[2] + red[3];
        v *= rsqrtf(tot / 128.f + EPSV) * ((which == 0) ? qn_w[d] : kn_w[d]);
    }

    float a = fabsf(v);
#pragma unroll
    for (int o = 16; o > 0; o >>= 1) a = fmaxf(a, __shfl_xor_sync(0xffffffffu, a, o));
    a = fmaxf(a, 1e-12f);
    int se = (int)floorf(log2f(a)) + 119;
    se = min(max(se, 0), 255);
    float scale = exp2f((float)(127 - se));
    float qv = fminf(fmaxf(v * scale, -448.f), 448.f);
    float dq = (float)__nv_fp8_e4m3(qv) * exp2f((float)(se - 127));

    size_t oidx = (((size_t)b * HH + h) * TT + t) * DD + d;
    if (which == 0)      Q[oidx] = dq;
    else if (which == 1) K[oidx] = dq;
    else                 V[oidx] = dq;
}

// ================= causal flash attention, fp32, 64x64 tiles =================
#define FLASH_SMEM 120832
__global__ __launch_bounds__(256) void flash_k(const float* __restrict__ Qg,
                                               const float* __restrict__ Kg,
                                               const float* __restrict__ Vg,
                                               float* __restrict__ O) {
    int qt = blockIdx.x, h = blockIdx.y, b = blockIdx.z;
    extern __shared__ float sm[];
    float* Qt = sm;
    float* Kt = Qt + 128 * 68;
    float* Vs = Kt + 128 * 68;
    float* Pt = Vs + 64 * 132;

    int tid = threadIdx.x, ty = tid >> 4, tx = tid & 15;
    const float* Qb = Qg + (((size_t)b * HH + h) * TT + qt * 64) * DD;
    const float* Kb = Kg + ((size_t)b * HH + h) * TT * DD;
    const float* Vb = Vg + ((size_t)b * HH + h) * TT * DD;

#pragma unroll
    for (int i = 0; i < 32; i++) {
        int lin = tid + i * 256;
        int r = lin >> 7, k = lin & 127;
        Qt[k * 68 + r] = Qb[(size_t)r * DD + k];
    }

    float o[4][8];
    float m_[4], l_[4];
#pragma unroll
    for (int i = 0; i < 4; i++) {
        m_[i] = -FLT_MAX; l_[i] = 0.f;
#pragma unroll
        for (int j = 0; j < 8; j++) o[i][j] = 0.f;
    }
    const float smscale = 0.08838834764831845f;

    for (int kv = 0; kv <= qt; kv++) {
        __syncthreads();
        const float* Kp = Kb + (size_t)kv * 64 * DD;
        const float* Vp = Vb + (size_t)kv * 64 * DD;
#pragma unroll
        for (int i = 0; i < 32; i++) {
            int lin = tid + i * 256;
            int r = lin >> 7, k = lin & 127;
            Kt[k * 68 + r] = Kp[(size_t)r * DD + k];
            Vs[r * 132 + k] = Vp[(size_t)r * DD + k];
        }
        __syncthreads();

        float s[4][4];
#pragma unroll
        for (int i = 0; i < 4; i++)
#pragma unroll
            for (int j = 0; j < 4; j++) s[i][j] = 0.f;

#pragma unroll 8
        for (int k = 0; k < 128; k++) {
            float4 aq = *(const float4*)&Qt[k * 68 + ty * 4];
            float4 bk = *(const float4*)&Kt[k * 68 + tx * 4];
            float av[4] = {aq.x, aq.y, aq.z, aq.w};
            float bv[4] = {bk.x, bk.y, bk.z, bk.w};
#pragma unroll
            for (int i = 0; i < 4; i++)
#pragma unroll
                for (int j = 0; j < 4; j++) s[i][j] += av[i] * bv[j];
        }

#pragma unroll
        for (int i = 0; i < 4; i++)
#pragma unroll
            for (int j = 0; j < 4; j++) {
                s[i][j] *= smscale;
                if (kv == qt && (tx * 4 + j) > (ty * 4 + i)) s[i][j] = -FLT_MAX;
            }

        float p[4][4];
#pragma unroll
        for (int i = 0; i < 4; i++) {
            float mt = fmaxf(fmaxf(s[i][0], s[i][1]), fmaxf(s[i][2], s[i][3]));
#pragma unroll
            for (int o2 = 8; o2 > 0; o2 >>= 1) mt = fmaxf(mt, __shfl_xor_sync(0xffffffffu, mt, o2));
            float mnew = fmaxf(m_[i], mt);
            float alpha = expf(m_[i] - mnew);
            float rs = 0.f;
#pragma unroll
            for (int j = 0; j < 4; j++) {
                p[i][j] = expf(s[i][j] - mnew);
                rs += p[i][j];
            }
#pragma unroll
            for (int o2 = 8; o2 > 0; o2 >>= 1) rs += __shfl_xor_sync(0xffffffffu, rs, o2);
            l_[i] = l_[i] * alpha + rs;
            m_[i] = mnew;
#pragma unroll
            for (int jj = 0; jj < 8; jj++) o[i][jj] *= alpha;
        }

#pragma unroll
        for (int i = 0; i < 4; i++)
#pragma unroll
            for (int j = 0; j < 4; j++)
                Pt[(tx * 4 + j) * 68 + ty * 4 + i] = p[i][j];
        __syncthreads();

#pragma unroll 4
        for (int j = 0; j < 64; j++) {
            float4 pv = *(const float4*)&Pt[j * 68 + ty * 4];
#pragma unroll
            for (int jj = 0; jj < 8; jj++) {
                float vv = Vs[j * 132 + tx + 16 * jj];
                o[0][jj] += pv.x * vv;
                o[1][jj] += pv.y * vv;
                o[2][jj] += pv.z * vv;
                o[3][jj] += pv.w * vv;
            }
        }
    }

#pragma unroll
    for (int i = 0; i < 4; i++) {
        int trow = qt * 64 + ty * 4 + i;
        float invl = 1.f / l_[i];
        size_t base = ((size_t)b * TT + trow) * CC + h * DD;
#pragma unroll
        for (int jj = 0; jj < 8; jj++)
            O[base + tx + 16 * jj] = o[i][jj] * invl;
    }
}

// ================= launcher =================
extern "C" void kernel_launch(void* const* d_in, const int* in_sizes, int n_in,
                              void* d_out, int out_size) {
    const float* x    = (const float*)d_in[0];
    const float* rope = (const float*)d_in[1];
    const float* ln1  = (const float*)d_in[2];
    const float* wqkv = (const float*)d_in[3];
    const float* qnw  = (const float*)d_in[4];
    const float* knw  = (const float*)d_in[5];
    const float* wout = (const float*)d_in[6];
    const float* ln2  = (const float*)d_in[7];
    const float* wfc1 = (const float*)d_in[8];
    const float* wfc2 = (const float*)d_in[9];
    float* out = (float*)d_out;

    float *qkv, *q, *k, *v, *attn, *x1;
    __nv_bfloat16 *xnh, *xnl, *ath, *atl, *hbh, *hbl;
    __nv_bfloat16 *wqh, *wql, *woh, *wol, *w1h, *w1l, *w2h, *w2l;
    cudaGetSymbolAddress((void**)&qkv,  g_qkv);
    cudaGetSymbolAddress((void**)&q,    g_q);
    cudaGetSymbolAddress((void**)&k,    g_k);
    cudaGetSymbolAddress((void**)&v,    g_v);
    cudaGetSymbolAddress((void**)&attn, g_attn);
    cudaGetSymbolAddress((void**)&x1,   g_x1);
    cudaGetSymbolAddress((void**)&xnh,  g_xn_hi);
    cudaGetSymbolAddress((void**)&xnl,  g_xn_lo);
    cudaGetSymbolAddress((void**)&ath,  g_at_hi);
    cudaGetSymbolAddress((void**)&atl,  g_at_lo);
    cudaGetSymbolAddress((void**)&hbh,  g_h_hi);
    cudaGetSymbolAddress((void**)&hbl,  g_h_lo);
    cudaGetSymbolAddress((void**)&wqh,  g_wq_hi);
    cudaGetSymbolAddress((void**)&wql,  g_wq_lo);
    cudaGetSymbolAddress((void**)&woh,  g_wo_hi);
    cudaGetSymbolAddress((void**)&wol,  g_wo_lo);
    cudaGetSymbolAddress((void**)&w1h,  g_w1_hi);
    cudaGetSymbolAddress((void**)&w1l,  g_w1_lo);
    cudaGetSymbolAddress((void**)&w2h,  g_w2_hi);
    cudaGetSymbolAddress((void**)&w2l,  g_w2_lo);

    cudaFuncSetAttribute(flash_k, cudaFuncAttributeMaxDynamicSharedMemorySize, FLASH_SMEM);
    cudaFuncSetAttribute(gemm_k<0>, cudaFuncAttributeMaxDynamicSharedMemorySize, GEMM_SMEM);
    cudaFuncSetAttribute(gemm_k<1>, cudaFuncAttributeMaxDynamicSharedMemorySize, GEMM_SMEM);
    cudaFuncSetAttribute(gemm_k<2>, cudaFuncAttributeMaxDynamicSharedMemorySize, GEMM_SMEM);

    // 0. weight prep
    wprep_k<<<dim3(3 * CC / 32, CC / 32), 256>>>(wqkv, wqh, wql, CC, 3 * CC);
    wprep_k<<<dim3(CC / 32, CC / 32), 256>>>(wout, woh, wol, CC, CC);
    wprep_k<<<dim3(FF / 32, CC / 32), 256>>>(wfc1, w1h, w1l, CC, FF);
    wprep_k<<<dim3(CC / 32, FF / 32), 256>>>(wfc2, w2h, w2l, FF, CC);

    // 1. ln1 -> hi/lo
    rmsnorm_k<<<NROWS, 256>>>(x, ln1, xnh, xnl);
    // 2. qkv = xn @ w_qkv
    gemm_k<0><<<dim3(3 * CC / 128, NROWS / 128), GT, GEMM_SMEM>>>(
        xnh, xnl, wqh, wql, qkv, nullptr, nullptr, nullptr, NROWS, 3 * CC, CC);
    // 3. rope + head-norm + mxfp8 qdq
    qkvpost_k<<<dim3(3 * HH, TT, BB), 128>>>(qkv, rope, qnw, knw, q, k, v);
    // 4. causal flash attention
    flash_k<<<dim3(TT / 64, HH, BB), 256, FLASH_SMEM>>>(q, k, v, attn);
    // 5. attn -> hi/lo
    cvt_hilo_k<<<2048, 256>>>(attn, ath, atl, NROWS * CC);
    // 6. x1 = x + attn @ w_out
    gemm_k<1><<<dim3(CC / 128, NROWS / 128), GT, GEMM_SMEM>>>(
        ath, atl, woh, wol, x1, x, nullptr, nullptr, NROWS, CC, CC);
    // 7. ln2 -> hi/lo
    rmsnorm_k<<<NROWS, 256>>>(x1, ln2, xnh, xnl);
    // 8. hb = srelu(xn @ w_fc1) -> hi/lo bf16
    gemm_k<2><<<dim3(FF / 128, NROWS / 128), GT, GEMM_SMEM>>>(
        xnh, xnl, w1h, w1l, nullptr, nullptr, hbh, hbl, NROWS, FF, CC);
    // 9. out = x1 + hb @ w_fc2
    gemm_k<1><<<dim3(CC / 128, NROWS / 128), GT, GEMM_SMEM>>>(
        hbh, hbl, w2h, w2l, out, x1, nullptr, nullptr, NROWS, CC, FF);
}